// round 7
// baseline (speedup 1.0000x reference)
#include <cuda_runtime.h>
#include <cstdint>
#include <math.h>

// ---------------------------------------------------------------------------
// SO3Reparameterize fused kernel, round 7.
// Root-cause from R1/R2/R6 metrics: the kernel was MIO-bound — 8B cp.async
// paid 8 LSU cycles per 8 bytes (~57k cyc/SM) on top of the compute LDS
// stream. Fix: stage x with cp.async.bulk (TMA engine, zero LSU cost; lane 0
// of each warp issues 64x 128B row-copies per chunk, completing on a per-slot
// mbarrier). x tile stored at 144B pitch -> conflict-free LDS.128 reads
// (8 lanes x 144B stride cover all 32 banks). 224 thr, 2 rows/thread,
// CHUNK_K=32, 3-slot ring, one __syncthreads + one mbar wait per chunk.
// ---------------------------------------------------------------------------

#define B_ROWS   65536
#define D_IN     1024
#define NBLK     148
#define NWARP    7
#define NTHR     (NWARP * 32)         // 224
#define ROWS_CAP 443                  // rows staged per CTA (nrows is 442/443)
#define CHUNK_K  32                   // k floats per chunk = 128B per row
#define NCHUNK   (D_IN / CHUNK_K)     // 32
#define PITCH_B  144                  // 128B data + 16B pad -> conflict-free LDS.128
#define STAGES   3
#define SLOT_B   (ROWS_CAP * PITCH_B) // 63792 B
#define WP_U64   (512 * 10)           // 512 k-pairs x (9 coeffs + pad) f32x2
#define WP_BYTES (WP_U64 * 8)         // 40960 B
#define XS_OFF   WP_BYTES
#define MBAR_OFF (WP_BYTES + STAGES * SLOT_B)     // 232336
#define SMEM_BYTES (MBAR_OFF + 48)                // 232384 <= 232448 opt-in max

typedef unsigned long long ull;

__device__ __forceinline__ void fma2(ull &acc, ull x, ull w) {
    asm("fma.rn.f32x2 %0, %1, %2, %0;" : "+l"(acc) : "l"(x), "l"(w));
}
__device__ __forceinline__ ull pack2(float lo, float hi) {
    ull r; asm("mov.b64 %0, {%1, %2};" : "=l"(r) : "f"(lo), "f"(hi)); return r;
}
__device__ __forceinline__ float2 unpack2(ull v) {
    float2 f; asm("mov.b64 {%0, %1}, %2;" : "=f"(f.x), "=f"(f.y) : "l"(v)); return f;
}

// ---- TMA bulk copy + mbarrier helpers -------------------------------------
__device__ __forceinline__ void bulk_g2s(uint32_t dst, const void* src, uint32_t bytes,
                                         uint32_t mbar) {
    asm volatile(
        "cp.async.bulk.shared::cluster.global.mbarrier::complete_tx::bytes "
        "[%0], [%1], %2, [%3];"
        :: "r"(dst), "l"(src), "r"(bytes), "r"(mbar) : "memory");
}
__device__ __forceinline__ void mbar_init(uint32_t mbar, uint32_t count) {
    asm volatile("mbarrier.init.shared.b64 [%0], %1;" :: "r"(mbar), "r"(count) : "memory");
}
__device__ __forceinline__ void mbar_arrive_expect(uint32_t mbar, uint32_t bytes) {
    asm volatile("mbarrier.arrive.expect_tx.shared.b64 _, [%0], %1;"
                 :: "r"(mbar), "r"(bytes) : "memory");
}
__device__ __forceinline__ void mbar_wait(uint32_t mbar, uint32_t parity) {
    uint32_t done;
    asm volatile(
        "{\n\t.reg .pred p;\n\t"
        "mbarrier.try_wait.parity.acquire.cta.shared::cta.b64 p, [%1], %2;\n\t"
        "selp.b32 %0, 1, 0, p;\n\t}"
        : "=r"(done) : "r"(mbar), "r"(parity) : "memory");
    if (!done) {
        asm volatile(
            "{\n\t.reg .pred P1;\n\t"
            "WAIT_LOOP_%=:\n\t"
            "mbarrier.try_wait.parity.acquire.cta.shared::cta.b64 P1, [%0], %1, 0x989680;\n\t"
            "@P1 bra.uni WAIT_DONE_%=;\n\t"
            "bra.uni WAIT_LOOP_%=;\n\t"
            "WAIT_DONE_%=:\n\t}"
            :: "r"(mbar), "r"(parity) : "memory");
    }
}

// ---- math -----------------------------------------------------------------
__device__ __forceinline__ float softplus_f(float x) {
    return fmaxf(x, 0.0f) + log1pf(expf(-fabsf(x)));
}

__device__ __forceinline__ void rodrigues(float vx, float vy, float vz, float R[9]) {
    float n2  = vx * vx + vy * vy + vz * vz;
    float th  = sqrtf(n2);
    float inv = 1.0f / th;                 // matches reference (no zero guard)
    float x = vx * inv, y = vy * inv, z = vz * inv;
    float s, c;
    sincosf(th, &s, &c);
    float C = 1.0f - c;
    float xC = x * C, yC = y * C, zC = z * C;
    float xs_ = x * s, ys_ = y * s, zs_ = z * s;
    R[0] = c + x * xC;  R[1] = x * yC - zs_; R[2] = x * zC + ys_;
    R[3] = x * yC + zs_; R[4] = c + y * yC;  R[5] = y * zC - xs_;
    R[6] = x * zC - ys_; R[7] = y * zC + xs_; R[8] = c + z * zC;
}

__device__ __forceinline__ void emit_row(const float y[9], int row,
                                         const float* __restrict__ eps,
                                         const float* __restrict__ bmu,
                                         const float* __restrict__ bd,
                                         const float* __restrict__ bl,
                                         float* __restrict__ out)
{
    float mux = y[0] + __ldg(bmu + 0);
    float muy = y[1] + __ldg(bmu + 1);
    float muz = y[2] + __ldg(bmu + 2);
    float d0 = softplus_f(y[3] + __ldg(bd + 0));
    float d1 = softplus_f(y[4] + __ldg(bd + 1));
    float d2 = softplus_f(y[5] + __ldg(bd + 2));
    float l0 = y[6] + __ldg(bl + 0);
    float l1 = y[7] + __ldg(bl + 1);
    float l2 = y[8] + __ldg(bl + 2);

    float e0 = __ldg(eps + (size_t)row * 3 + 0);
    float e1 = __ldg(eps + (size_t)row * 3 + 1);
    float e2 = __ldg(eps + (size_t)row * 3 + 2);

    float s0 = sqrtf(d0) * e0;
    float s1 = sqrtf(d1) * e1;
    float s2 = sqrtf(d2) * e2;

    float v0 = s0;
    float v1 = l0 * s0 + s1;
    float v2 = l1 * s0 + l2 * s1 + s2;

    float Rm[9], Rv[9];
    rodrigues(mux, muy, muz, Rm);
    rodrigues(v0, v1, v2, Rv);

    float* o = out + (size_t)row * 9;
#pragma unroll
    for (int i = 0; i < 3; ++i) {
#pragma unroll
        for (int j = 0; j < 3; ++j) {
            o[i * 3 + j] = Rm[i * 3 + 0] * Rv[0 * 3 + j]
                         + Rm[i * 3 + 1] * Rv[1 * 3 + j]
                         + Rm[i * 3 + 2] * Rv[2 * 3 + j];
        }
    }
}

// 9-output dot step for one k-pair, two rows sharing the W fetch
__device__ __forceinline__ void dot9(ull accA[9], ull accB[9], ull xa, ull xb,
                                     const ull* __restrict__ w) {
    ulonglong2 w01 = *(const ulonglong2*)(w + 0);   // broadcast LDS.128
    ulonglong2 w23 = *(const ulonglong2*)(w + 2);
    ulonglong2 w45 = *(const ulonglong2*)(w + 4);
    ulonglong2 w67 = *(const ulonglong2*)(w + 6);
    ull        w8  = w[8];
    fma2(accA[0], xa, w01.x); fma2(accB[0], xb, w01.x);
    fma2(accA[1], xa, w01.y); fma2(accB[1], xb, w01.y);
    fma2(accA[2], xa, w23.x); fma2(accB[2], xb, w23.x);
    fma2(accA[3], xa, w23.y); fma2(accB[3], xb, w23.y);
    fma2(accA[4], xa, w45.x); fma2(accB[4], xb, w45.x);
    fma2(accA[5], xa, w45.y); fma2(accB[5], xb, w45.y);
    fma2(accA[6], xa, w67.x); fma2(accB[6], xb, w67.x);
    fma2(accA[7], xa, w67.y); fma2(accB[7], xb, w67.y);
    fma2(accA[8], xa, w8);    fma2(accB[8], xb, w8);
}

__global__ void __launch_bounds__(NTHR, 1)
so3_kernel(const float* __restrict__ x,   const float* __restrict__ eps,
           const float* __restrict__ Wmu, const float* __restrict__ bmu,
           const float* __restrict__ Wd,  const float* __restrict__ bd,
           const float* __restrict__ Wl,  const float* __restrict__ bl,
           float* __restrict__ out)
{
    extern __shared__ unsigned char smem[];
    ull* Wp = (ull*)smem;                          // [512 pairs][10] f32x2
    unsigned char* xs = smem + XS_OFF;             // [STAGES][ROWS_CAP][PITCH_B]
    const uint32_t smem_s = (uint32_t)__cvta_generic_to_shared(smem);
    const uint32_t xs_s   = smem_s + XS_OFF;
    const uint32_t mbar0  = smem_s + MBAR_OFF;     // 3 mbarriers, 8B each

    const int t    = threadIdx.x;
    const int w    = t >> 5;
    const int lane = t & 31;
    const int b    = blockIdx.x;
    const int start = (int)(((long long)b * B_ROWS) / NBLK);
    const int end   = (int)(((long long)(b + 1) * B_ROWS) / NBLK);
    const int nrows = end - start;                 // 442 or 443
    // Staged rows 0..442: global row start+442 <= 65535 for every block, so
    // unconditional staging is in-bounds. (start+442 == end-1 when nrows=443;
    // when nrows=442, start+442 == end <= 65535 since only the last block
    // reaches end==65536 and it has nrows=443.)

    // ---- mbarrier init (count = NWARP arrivals per phase)
    if (t == 0) {
#pragma unroll
        for (int i = 0; i < STAGES; ++i) mbar_init(mbar0 + 8 * i, NWARP);
    }
    __syncthreads();

    // ---- staging: lane 0 of warp w copies rows [64w, 64w+wcnt)
    const int wrow0 = w * 64;
    const int wcnt  = (wrow0 + 64 <= ROWS_CAP) ? 64 : (ROWS_CAP - wrow0);  // 64 or 59
    const char* gsrc0 = (const char*)(x + (size_t)(start + wrow0) * D_IN);

#define STAGE(ch_, slot_)                                                      \
    do {                                                                       \
        if (lane == 0) {                                                       \
            uint32_t mb_ = mbar0 + 8 * (slot_);                                \
            mbar_arrive_expect(mb_, (uint32_t)(wcnt * 128));                   \
            uint32_t d_ = xs_s + (uint32_t)(slot_) * SLOT_B                    \
                        + (uint32_t)(wrow0 * PITCH_B);                         \
            const char* s_ = gsrc0 + (size_t)(ch_) * 128;                      \
            for (int j_ = 0; j_ < wcnt; ++j_)                                  \
                bulk_g2s(d_ + (uint32_t)(j_ * PITCH_B),                        \
                         s_ + (size_t)j_ * (D_IN * 4), 128, mb_);              \
        }                                                                      \
    } while (0)

    // ---- prologue: chunks 0 and 1 in flight
    STAGE(0, 0);
    STAGE(1, 1);

    // ---- pack W into smem as k-pair f32x2 (overlaps TMA of chunks 0/1)
    for (int i = t; i < WP_U64; i += NTHR) {
        int p = i / 10, c = i % 10;
        int k0 = 2 * p;
        float lo = 0.0f, hi = 0.0f;
        if (c < 3)      { lo = __ldg(Wmu + k0 * 3 + c);       hi = __ldg(Wmu + (k0 + 1) * 3 + c); }
        else if (c < 6) { lo = __ldg(Wd  + k0 * 3 + (c - 3)); hi = __ldg(Wd  + (k0 + 1) * 3 + (c - 3)); }
        else if (c < 9) { lo = __ldg(Wl  + k0 * 3 + (c - 6)); hi = __ldg(Wl  + (k0 + 1) * 3 + (c - 6)); }
        Wp[i] = pack2(lo, hi);
    }
    // (W visibility to all threads is guaranteed by the __syncthreads inside
    //  the first loop iteration below.)

    ull accA[9], accB[9];
#pragma unroll
    for (int c = 0; c < 9; ++c) { accA[c] = 0ull; accB[c] = 0ull; }

    const int rA = t;                              // 0..223, always valid
    const int rB = (t + NTHR < ROWS_CAP) ? (t + NTHR) : (ROWS_CAP - 1);  // clamped read

    // ---- main loop: 32 chunks, 3-slot ring, TMA prefetch depth 2
    for (int ch = 0; ch < NCHUNK; ++ch) {
        const int slot = ch % STAGES;
        mbar_wait(mbar0 + 8 * slot, (ch / STAGES) & 1);   // chunk ch landed
        __syncthreads();                                  // all done reading ch-1

        const int nc = ch + 2;                            // prefetch before compute
        if (nc < NCHUNK) STAGE(nc, nc % STAGES);

        const unsigned char* sb = xs + (size_t)slot * SLOT_B;
        const float4* pa = (const float4*)(sb + rA * PITCH_B);
        const float4* pb = (const float4*)(sb + rB * PITCH_B);
        const ull* wrow = Wp + (size_t)ch * 16 * 10;      // 16 pairs/chunk

#pragma unroll
        for (int u = 0; u < 8; ++u) {
            ulonglong2 xa = ((const ulonglong2*)pa)[u];   // conflict-free LDS.128
            ulonglong2 xb = ((const ulonglong2*)pb)[u];
            const ull* wp0 = wrow + (2 * u) * 10;
            dot9(accA, accB, xa.x, xb.x, wp0);            // pair 2u
            dot9(accA, accB, xa.y, xb.y, wp0 + 10);       // pair 2u+1
        }
    }
#undef STAGE

    // ---- epilogue: per-row SO(3) math, pure registers
    {
        float y[9];
#pragma unroll
        for (int c = 0; c < 9; ++c) { float2 f = unpack2(accA[c]); y[c] = f.x + f.y; }
        emit_row(y, start + rA, eps, bmu, bd, bl, out);   // rA < 224 < nrows
    }
    if (t + NTHR < nrows) {
        float y[9];
#pragma unroll
        for (int c = 0; c < 9; ++c) { float2 f = unpack2(accB[c]); y[c] = f.x + f.y; }
        emit_row(y, start + t + NTHR, eps, bmu, bd, bl, out);
    }
}

extern "C" void kernel_launch(void* const* d_in, const int* in_sizes, int n_in,
                              void* d_out, int out_size)
{
    cudaFuncSetAttribute(so3_kernel, cudaFuncAttributeMaxDynamicSharedMemorySize, SMEM_BYTES);
    const float* x   = (const float*)d_in[0];
    const float* eps = (const float*)d_in[1];
    const float* Wmu = (const float*)d_in[2];
    const float* bmu = (const float*)d_in[3];
    const float* Wd  = (const float*)d_in[4];
    const float* bd  = (const float*)d_in[5];
    const float* Wl  = (const float*)d_in[6];
    const float* bl  = (const float*)d_in[7];

    so3_kernel<<<NBLK, NTHR, SMEM_BYTES>>>(x, eps, Wmu, bmu, Wd, bd, Wl, bl, (float*)d_out);
}